// round 15
// baseline (speedup 1.0000x reference)
#include <cuda_runtime.h>
#include <math.h>

#define BGRAPH 128
#define NPG    512
#define NNODES (BGRAPH*NPG)
#define EPG    (NPG*16)
#define NEDGE  (NNODES*16)
#define NT     1024
#define NW     32

// cross-kernel scratch
__device__ float g_u[2][3][BGRAPH*640];
__device__ int   g_done[BGRAPH];        // zero-initialized; reset each launch

// SMEM byte offsets for k_fused
#define OFF_XBUF 0          // 512*64 f = 131072
#define OFF_YBUF 131072     // 512*32 f =  65536
#define OFF_CSR  196608     // ushort[9728] = 19456
#define OFF_OFFS 216064     // ushort[513] -> 1032
#define OFF_INV  217096     // float[512] = 2048
#define OFF_PAD  219144     // uchar[512] = 512
#define OFF_SCR  219656     // int[1040] = 4160
#define SMEM_BYTES 223816

// ---------------- XW0: FO=64, lane owns column pair (2l, 2l+1), float2 W loads ----------------
template<int R>
__device__ __forceinline__ void xw0_pair(
    const float* __restrict__ Xs, int row0, int nrows,
    float* __restrict__ Ys, const float* __restrict__ W,
    const float* __restrict__ invsh, int warp, int lane)
{
    const int c0 = 2 * lane;
    for (int grp = warp; grp < nrows / R; grp += NW) {
        int r0 = grp * R;
        float a0[R], a1[R];
        #pragma unroll
        for (int r = 0; r < R; r++) { a0[r] = 0.f; a1[r] = 0.f; }
        #pragma unroll 4
        for (int k = 0; k < 64; k += 4) {
            float2 w[4];
            #pragma unroll
            for (int q = 0; q < 4; q++)
                w[q] = __ldg((const float2*)(W + (k + q) * 64 + c0));
            #pragma unroll
            for (int r = 0; r < R; r++) {
                const float4 xv = *(const float4*)(Xs + (r0 + r) * 64 + k);
                a0[r] = fmaf(xv.x, w[0].x, a0[r]);  a1[r] = fmaf(xv.x, w[0].y, a1[r]);
                a0[r] = fmaf(xv.y, w[1].x, a0[r]);  a1[r] = fmaf(xv.y, w[1].y, a1[r]);
                a0[r] = fmaf(xv.z, w[2].x, a0[r]);  a1[r] = fmaf(xv.z, w[2].y, a1[r]);
                a0[r] = fmaf(xv.w, w[3].x, a0[r]);  a1[r] = fmaf(xv.w, w[3].y, a1[r]);
            }
        }
        #pragma unroll
        for (int r = 0; r < R; r++) {
            int n = row0 + r0 + r;
            float inv = invsh[n];
            float2 o; o.x = a0[r] * inv; o.y = a1[r] * inv;
            *(float2*)(Ys + n * 64 + c0) = o;
        }
    }
}

// ---------------- XW stage from SMEM (layers 1,2; scalar cols) ----------------
template<int FI, int FO, int R>
__device__ __forceinline__ void xw_stage(
    const float* __restrict__ Xs, int xstride,
    float* __restrict__ Ys, const float* __restrict__ W,
    const float* __restrict__ invsh, int warp, int lane)
{
    const int c0 = lane & (FO - 1);
    for (int grp = warp; grp < NPG / R; grp += NW) {
        int r0 = grp * R;
        float acc0[R];
        #pragma unroll
        for (int r = 0; r < R; r++) acc0[r] = 0.f;
        #pragma unroll 4
        for (int k = 0; k < FI; k += 4) {
            float w0[4];
            #pragma unroll
            for (int q = 0; q < 4; q++) w0[q] = __ldg(W + (k + q) * FO + c0);
            #pragma unroll
            for (int r = 0; r < R; r++) {
                const float4 xv = *(const float4*)(Xs + (r0 + r) * xstride + k);
                acc0[r] = fmaf(xv.x, w0[0], acc0[r]);
                acc0[r] = fmaf(xv.y, w0[1], acc0[r]);
                acc0[r] = fmaf(xv.z, w0[2], acc0[r]);
                acc0[r] = fmaf(xv.w, w0[3], acc0[r]);
            }
        }
        #pragma unroll
        for (int r = 0; r < R; r++) {
            int n = r0 + r;
            if (FO >= 32 || lane < FO) Ys[n * FO + c0] = acc0[r] * invsh[n];
        }
    }
}

// ---------------- aggregation FO=32, direct write ----------------
__device__ __forceinline__ void agg32(
    const float* __restrict__ Ys, float* __restrict__ Out,
    const ushort4* __restrict__ csr4, const unsigned short* __restrict__ offsh,
    const float* __restrict__ invsh, const unsigned char* __restrict__ padsh,
    const float* __restrict__ bias, int warp, int lane)
{
    const float b0 = __ldg(bias + lane);
    for (int n = warp; n < NPG; n += NW) {
        int q0 = offsh[n] >> 2, q1 = offsh[n + 1] >> 2;
        float a0 = 0.f;
        for (int q = q0; q < q1; q++) {
            ushort4 ix = csr4[q];
            a0 += Ys[ix.x * 32 + lane];
            a0 += Ys[ix.y * 32 + lane];
            a0 += Ys[ix.z * 32 + lane];
            a0 += Ys[ix.w * 32 + lane];
        }
        float corr = 1.f - (float)padsh[n];
        a0 = fmaf(corr, Ys[n * 32 + lane], a0);
        Out[n * 32 + lane] = fmaxf(a0 * invsh[n] + b0, 0.f);
    }
}

// ---------------- resize-tap projection ----------------
template<int FO>
__device__ __forceinline__ void taps(const float* __restrict__ Hs, int stride,
                                     float* __restrict__ uout, int tid)
{
    for (int t = tid; t < 10 * FO; t += NT) {
        int p = t / FO, d = t % FO;
        float c = (p + 0.5f) * 51.2f - 0.5f;
        int i0 = (int)floorf(c);
        float w = c - (float)i0;
        uout[p * 64 + d] = Hs[i0 * stride + d] * (1.f - w) + Hs[(i0 + 1) * stride + d] * w;
    }
}

// ---------------- fused per-(graph,side) kernel + inline head on 2nd arrival ----------------
__global__ void __launch_bounds__(NT, 1)
k_fused(const float* __restrict__ x0, const float* __restrict__ x1,
        const float* __restrict__ W0, const float* __restrict__ b0,
        const float* __restrict__ W1, const float* __restrict__ b1,
        const float* __restrict__ W2, const float* __restrict__ b2,
        const int* __restrict__ ei, const int* __restrict__ ej,
        const float* __restrict__ cw0, const float* __restrict__ cb0,
        const float* __restrict__ cw1, const float* __restrict__ cb1,
        const float* __restrict__ cw2, const float* __restrict__ cb2,
        const float* __restrict__ mw0, const float* __restrict__ mb0,
        const float* __restrict__ mw1, const float* __restrict__ mb1,
        const float* __restrict__ mw2, const float* __restrict__ mb2,
        const float* __restrict__ mw3, const float* __restrict__ mb3,
        const float* __restrict__ mw4, const float* __restrict__ mb4,
        const float* __restrict__ sw,  const float* __restrict__ sb,
        float* __restrict__ out)
{
    extern __shared__ char smraw[];
    float*          xbuf  = (float*)(smraw + OFF_XBUF);
    float*          ybuf  = (float*)(smraw + OFF_YBUF);
    unsigned short* csr   = (unsigned short*)(smraw + OFF_CSR);
    const ushort4*  csr4  = (const ushort4*)csr;
    unsigned short* offsh = (unsigned short*)(smraw + OFF_OFFS);
    float*          invsh = (float*)(smraw + OFF_INV);
    unsigned char*  padsh = (unsigned char*)(smraw + OFF_PAD);
    int*            cnt   = (int*)(smraw + OFF_SCR);   // [512]
    int*            cur   = cnt + 512;                 // [512]
    int*            wtot  = cnt + 1024;                // [16]
    __shared__ int  lastflag;

    const int side = blockIdx.y, g = blockIdx.x;
    const int tid = threadIdx.x, warp = tid >> 5, lane = tid & 31;
    const int* E    = side ? ej : ei;
    const int* esrc = E + g * EPG;
    const int* edst = E + NEDGE + g * EPG;
    const float* Xg = (side ? x1 : x0) + (size_t)g * NPG * 64;

    // ---- count pass: cache src/dst into ybuf as ushort, count degrees ----
    unsigned short* srcc = (unsigned short*)ybuf;   // [8192]
    unsigned short* dstc = srcc + EPG;              // [8192]
    if (tid < 512) cnt[tid] = 0;
    __syncthreads();
    for (int e = tid; e < EPG; e += NT) {
        int sv = esrc[e] & (NPG - 1), dv = edst[e] & (NPG - 1);
        srcc[e] = (unsigned short)sv;
        dstc[e] = (unsigned short)dv;
        atomicAdd(&cnt[dv], 1);
    }
    __syncthreads();

    // ---- scan of padded degrees ----
    int deg = 0, pc = 0, s_incl = 0, off = 0;
    if (tid < 512) {
        deg = cnt[tid];
        pc  = (deg + 3) & ~3;
        s_incl = pc;
        #pragma unroll
        for (int d = 1; d < 32; d <<= 1) {
            int v = __shfl_up_sync(0xffffffffu, s_incl, d);
            if (lane >= d) s_incl += v;
        }
        if (lane == 31) wtot[warp] = s_incl;
    }
    __syncthreads();
    if (tid < 16) {
        int t = wtot[tid];
        #pragma unroll
        for (int d = 1; d < 16; d <<= 1) {
            int v = __shfl_up_sync(0x0000ffffu, t, d);
            if (tid >= d) t += v;
        }
        wtot[tid] = t;
    }
    __syncthreads();
    if (tid < 512) {
        int base = warp ? wtot[warp - 1] : 0;
        off = base + s_incl - pc;
        offsh[tid] = (unsigned short)off;
        if (tid == 511) offsh[512] = (unsigned short)(off + pc);
        invsh[tid] = rsqrtf((float)deg + 1.0f);
        padsh[tid] = (unsigned char)(pc - deg);
        cur[tid] = off;
    }
    __syncthreads();

    // ---- fill pass: SMEM only ----
    for (int e = tid; e < EPG; e += NT) {
        int dv = dstc[e];
        int p = atomicAdd(&cur[dv], 1);
        csr[p] = srcc[e];
    }
    if (tid < 512)
        for (int t = deg; t < pc; t++) csr[off + t] = (unsigned short)tid;
    __syncthreads();

    // ---- layer 0 XW: stage X through ybuf in two 256-row chunks ----
    for (int ch = 0; ch < 2; ch++) {
        const float4* src = (const float4*)(Xg + (size_t)ch * 256 * 64);
        float4* dst = (float4*)ybuf;
        for (int i = tid; i < 4096; i += NT) dst[i] = src[i];
        __syncthreads();
        xw0_pair<8>(ybuf, ch * 256, 256, xbuf, W0, invsh, warp, lane);
        __syncthreads();
    }

    // ---- agg0: float2 gathers (lane owns channel pair 2l,2l+1), stage in regs, write back ----
    {
        float2 h[16];
        const int l2 = 2 * lane;
        const float2 bb = *(const float2*)(b0 + l2);
        #pragma unroll
        for (int it = 0; it < 16; it++) {
            int n = warp + it * NW;
            int q0 = offsh[n] >> 2, q1 = offsh[n + 1] >> 2;
            float a0 = 0.f, a1 = 0.f;
            for (int q = q0; q < q1; q++) {
                ushort4 ix = csr4[q];
                float2 vx = *(const float2*)(xbuf + ix.x * 64 + l2);
                float2 vy = *(const float2*)(xbuf + ix.y * 64 + l2);
                float2 vz = *(const float2*)(xbuf + ix.z * 64 + l2);
                float2 vw = *(const float2*)(xbuf + ix.w * 64 + l2);
                a0 += vx.x; a1 += vx.y;
                a0 += vy.x; a1 += vy.y;
                a0 += vz.x; a1 += vz.y;
                a0 += vw.x; a1 += vw.y;
            }
            float corr = 1.f - (float)padsh[n];
            float2 vs = *(const float2*)(xbuf + n * 64 + l2);
            a0 = fmaf(corr, vs.x, a0);
            a1 = fmaf(corr, vs.y, a1);
            float inv = invsh[n];
            h[it].x = fmaxf(a0 * inv + bb.x, 0.f);
            h[it].y = fmaxf(a1 * inv + bb.y, 0.f);
        }
        __syncthreads();
        #pragma unroll
        for (int it = 0; it < 16; it++) {
            int n = warp + it * NW;
            *(float2*)(xbuf + n * 64 + l2) = h[it];
        }
        __syncthreads();
    }

    // ---- taps0 + XW1 ----
    taps<64>(xbuf, 64, &g_u[side][0][g * 640], tid);
    xw_stage<64, 32, 8>(xbuf, 64, ybuf, W1, invsh, warp, lane);
    __syncthreads();

    // ---- agg1: ybuf -> xbuf ----
    agg32(ybuf, xbuf, csr4, offsh, invsh, padsh, b1, warp, lane);
    __syncthreads();

    // ---- taps1 + XW2 ----
    taps<32>(xbuf, 32, &g_u[side][1][g * 640], tid);
    xw_stage<32, 16, 8>(xbuf, 32, ybuf, W2, invsh, warp, lane);
    __syncthreads();

    // ---- fused agg2 + taps2: only the 20 tap rows ----
    float* tmp = (float*)cnt;
    if (warp < 20) {
        int p = warp >> 1;
        float c = (p + 0.5f) * 51.2f - 0.5f;
        int i0 = (int)floorf(c);
        int r = i0 + (warp & 1);
        int c0 = lane & 15;
        int q0 = offsh[r] >> 2, q1 = offsh[r + 1] >> 2;
        float a = 0.f;
        for (int q = q0; q < q1; q++) {
            ushort4 ix = csr4[q];
            a += ybuf[ix.x * 16 + c0];
            a += ybuf[ix.y * 16 + c0];
            a += ybuf[ix.z * 16 + c0];
            a += ybuf[ix.w * 16 + c0];
        }
        a = fmaf(1.f - (float)padsh[r], ybuf[r * 16 + c0], a);
        tmp[warp * 16 + c0] = a * invsh[r] + __ldg(b2 + c0);
    }
    __syncthreads();
    if (tid < 160) {
        int p = tid >> 4, d = tid & 15;
        float c = (p + 0.5f) * 51.2f - 0.5f;
        int i0 = (int)floorf(c);
        float w = c - (float)i0;
        g_u[side][2][g * 640 + p * 64 + d] =
            tmp[(2 * p) * 16 + d] * (1.f - w) + tmp[(2 * p + 1) * 16 + d] * w;
    }

    // ================= arrival: second block per graph runs the head =================
    __syncthreads();
    if (tid == 0) {
        __threadfence();
        lastflag = (atomicAdd(&g_done[g], 1) == 1);
    }
    __syncthreads();
    if (!lastflag) return;

    // SMEM reuse (everything above is dead)
    float* uiH   = (float*)smraw;        // [3*640]
    float* ujH   = uiH + 1920;           // [3*640]
    float* simH  = ujH + 1920;           // [300]
    float* featH = simH + 300;           // [2400]
    float* redH  = featH + 2400;         // [32*32]
    float* cwH   = redH + 1024;          // [216]
    float* cbH   = cwH + 216;            // [24]

    for (int t = tid; t < 1920; t += NT) {
        int l = t / 640, r = t - l * 640;
        uiH[t] = __ldcg(&g_u[0][l][g * 640 + r]);
        ujH[t] = __ldcg(&g_u[1][l][g * 640 + r]);
    }
    if (tid < 72) {
        cwH[tid]       = __ldg(cw0 + tid);
        cwH[72 + tid]  = __ldg(cw1 + tid);
        cwH[144 + tid] = __ldg(cw2 + tid);
    }
    if (tid >= 96 && tid < 104) {
        int c = tid - 96;
        cbH[c]      = __ldg(cb0 + c);
        cbH[8 + c]  = __ldg(cb1 + c);
        cbH[16 + c] = __ldg(cb2 + c);
    }
    __syncthreads();

    // sims: 300 warp-tasks over 32 warps
    for (int ent = warp; ent < 300; ent += NW) {
        int l = ent / 100, e = ent - l * 100;
        int p = e / 10, q = e - p * 10;
        int fo = 64 >> l;
        float s = 0.f;
        for (int d = lane; d < fo; d += 32)
            s = fmaf(uiH[l * 640 + p * 64 + d], ujH[l * 640 + q * 64 + d], s);
        #pragma unroll
        for (int o = 16; o; o >>= 1) s += __shfl_xor_sync(0xffffffffu, s, o);
        if (lane == 0) simH[ent] = s;
    }
    __syncthreads();

    // conv3x3 + relu -> feat[2400]
    for (int t = tid; t < 2400; t += NT) {
        int l = t / 800, u = t - l * 800;
        int ch = u / 100, rc = u - ch * 100, r = rc / 10, c = rc - r * 10;
        float acc = cbH[l * 8 + ch];
        #pragma unroll
        for (int dr = 0; dr < 3; dr++)
            #pragma unroll
            for (int dc = 0; dc < 3; dc++) {
                int rr = r + dr - 1, cc = c + dc - 1;
                if (rr >= 0 && rr < 10 && cc >= 0 && cc < 10)
                    acc = fmaf(cwH[l * 72 + ch * 9 + dr * 3 + dc], simH[l * 100 + rr * 10 + cc], acc);
            }
        featH[t] = fmaxf(acc, 0.f);
    }
    __syncthreads();

    // MLP0: 2400 -> 32, 32-way split-K
    {
        float acc = 0.f;
        for (int k = warp; k < 2400; k += 32)
            acc = fmaf(featH[k], __ldg(mw0 + k * 32 + lane), acc);
        redH[warp * 32 + lane] = acc;
    }
    __syncthreads();

    if (warp == 0) {
        float s = __ldg(mb0 + lane);
        #pragma unroll
        for (int p = 0; p < 32; p++) s += redH[p * 32 + lane];
        float a0v = fmaxf(s, 0.f);

        float a1v = (lane < 16) ? __ldg(mb1 + lane) : 0.f;
        #pragma unroll
        for (int k = 0; k < 32; k++) {
            float v = __shfl_sync(0xffffffffu, a0v, k);
            if (lane < 16) a1v = fmaf(v, __ldg(mw1 + k * 16 + lane), a1v);
        }
        a1v = fmaxf(a1v, 0.f);

        float a2v = (lane < 8) ? __ldg(mb2 + lane) : 0.f;
        #pragma unroll
        for (int k = 0; k < 16; k++) {
            float v = __shfl_sync(0xffffffffu, a1v, k);
            if (lane < 8) a2v = fmaf(v, __ldg(mw2 + k * 8 + lane), a2v);
        }
        a2v = fmaxf(a2v, 0.f);

        float a3v = (lane < 4) ? __ldg(mb3 + lane) : 0.f;
        #pragma unroll
        for (int k = 0; k < 8; k++) {
            float v = __shfl_sync(0xffffffffu, a2v, k);
            if (lane < 4) a3v = fmaf(v, __ldg(mw3 + k * 4 + lane), a3v);
        }
        a3v = fmaxf(a3v, 0.f);

        float v0 = __shfl_sync(0xffffffffu, a3v, 0);
        float v1 = __shfl_sync(0xffffffffu, a3v, 1);
        float v2 = __shfl_sync(0xffffffffu, a3v, 2);
        float v3 = __shfl_sync(0xffffffffu, a3v, 3);
        if (lane == 0) {
            float s4 = __ldg(mb4);
            s4 = fmaf(v0, __ldg(mw4 + 0), s4);
            s4 = fmaf(v1, __ldg(mw4 + 1), s4);
            s4 = fmaf(v2, __ldg(mw4 + 2), s4);
            s4 = fmaf(v3, __ldg(mw4 + 3), s4);
            float f = fmaxf(s4, 0.f);
            float sc = f * __ldg(sw) + __ldg(sb);
            out[g] = 1.f / (1.f + expf(-sc));
            g_done[g] = 0;   // reset for next graph replay
        }
    }
}

// ---------------- launch ----------------
extern "C" void kernel_launch(void* const* d_in, const int* in_sizes, int n_in,
                              void* d_out, int out_size) {
    const float* x_i = (const float*)d_in[0];
    const float* x_j = (const float*)d_in[1];
    const float* gw0 = (const float*)d_in[2];  const float* gb0 = (const float*)d_in[3];
    const float* gw1 = (const float*)d_in[4];  const float* gb1 = (const float*)d_in[5];
    const float* gw2 = (const float*)d_in[6];  const float* gb2 = (const float*)d_in[7];
    const float* cw0 = (const float*)d_in[8];  const float* cb0 = (const float*)d_in[9];
    const float* cw1 = (const float*)d_in[10]; const float* cb1 = (const float*)d_in[11];
    const float* cw2 = (const float*)d_in[12]; const float* cb2 = (const float*)d_in[13];
    const float* mw0 = (const float*)d_in[14]; const float* mb0 = (const float*)d_in[15];
    const float* mw1 = (const float*)d_in[16]; const float* mb1 = (const float*)d_in[17];
    const float* mw2 = (const float*)d_in[18]; const float* mb2 = (const float*)d_in[19];
    const float* mw3 = (const float*)d_in[20]; const float* mb3 = (const float*)d_in[21];
    const float* mw4 = (const float*)d_in[22]; const float* mb4 = (const float*)d_in[23];
    const float* sw  = (const float*)d_in[24]; const float* sb  = (const float*)d_in[25];
    const int*   ei  = (const int*)d_in[26];
    const int*   ej  = (const int*)d_in[27];

    cudaFuncSetAttribute(k_fused, cudaFuncAttributeMaxDynamicSharedMemorySize, SMEM_BYTES);

    k_fused<<<dim3(BGRAPH, 2), NT, SMEM_BYTES>>>(
        x_i, x_j, gw0, gb0, gw1, gb1, gw2, gb2, ei, ej,
        cw0, cb0, cw1, cb1, cw2, cb2,
        mw0, mb0, mw1, mb1, mw2, mb2, mw3, mb3, mw4, mb4,
        sw, sb, (float*)d_out);
}

// round 16
// speedup vs baseline: 1.0423x; 1.0423x over previous
#include <cuda_runtime.h>
#include <math.h>

#define BGRAPH 128
#define NPG    512
#define NNODES (BGRAPH*NPG)
#define EPG    (NPG*16)
#define NEDGE  (NNODES*16)
#define NT     1024
#define NW     32

// cross-kernel scratch
__device__ float g_u[2][3][BGRAPH*640];
__device__ int   g_done[BGRAPH];        // zero-initialized; reset each launch

// SMEM byte offsets for k_fused
#define OFF_XBUF 0          // 512*64 f = 131072 (X in-place -> Y0 -> h0)
#define OFF_YBUF 131072     // 512*32 f =  65536 (edge ushort cache during build; Y1 after)
#define OFF_CSR  196608     // ushort[9728] = 19456
#define OFF_OFFS 216064     // ushort[513] -> 1032
#define OFF_INV  217096     // float[512] = 2048
#define OFF_PAD  219144     // uchar[512] = 512
#define OFF_SCR  219656     // int[1040] = 4160
#define SMEM_BYTES 223816

// ---------------- XW0: in-place, FO=64, lane owns col pair (2l,2l+1), float2 W loads ----------------
__device__ __forceinline__ void xw0_pair_inplace(
    float* Xs /* == Ys */, const float* __restrict__ W,
    const float* __restrict__ invsh, int warp, int lane)
{
    const int c0 = 2 * lane;
    for (int grp = warp; grp < 64; grp += NW) {
        int r0 = grp * 8;
        float a0[8], a1[8];
        #pragma unroll
        for (int r = 0; r < 8; r++) { a0[r] = 0.f; a1[r] = 0.f; }
        #pragma unroll 4
        for (int k = 0; k < 64; k += 4) {
            float2 w[4];
            #pragma unroll
            for (int q = 0; q < 4; q++)
                w[q] = __ldg((const float2*)(W + (k + q) * 64 + c0));
            #pragma unroll
            for (int r = 0; r < 8; r++) {
                const float4 xv = *(const float4*)(Xs + (r0 + r) * 64 + k);
                a0[r] = fmaf(xv.x, w[0].x, a0[r]);  a1[r] = fmaf(xv.x, w[0].y, a1[r]);
                a0[r] = fmaf(xv.y, w[1].x, a0[r]);  a1[r] = fmaf(xv.y, w[1].y, a1[r]);
                a0[r] = fmaf(xv.z, w[2].x, a0[r]);  a1[r] = fmaf(xv.z, w[2].y, a1[r]);
                a0[r] = fmaf(xv.w, w[3].x, a0[r]);  a1[r] = fmaf(xv.w, w[3].y, a1[r]);
            }
        }
        #pragma unroll
        for (int r = 0; r < 8; r++) {
            int n = r0 + r;
            float inv = invsh[n];
            float2 o; o.x = a0[r] * inv; o.y = a1[r] * inv;
            *(float2*)(Xs + n * 64 + c0) = o;
        }
    }
}

// ---------------- XW stage from SMEM (layers 1,2; scalar cols) ----------------
template<int FI, int FO, int R>
__device__ __forceinline__ void xw_stage(
    const float* __restrict__ Xs, int xstride,
    float* __restrict__ Ys, const float* __restrict__ W,
    const float* __restrict__ invsh, int warp, int lane)
{
    const int c0 = lane & (FO - 1);
    for (int grp = warp; grp < NPG / R; grp += NW) {
        int r0 = grp * R;
        float acc0[R];
        #pragma unroll
        for (int r = 0; r < R; r++) acc0[r] = 0.f;
        #pragma unroll 4
        for (int k = 0; k < FI; k += 4) {
            float w0[4];
            #pragma unroll
            for (int q = 0; q < 4; q++) w0[q] = __ldg(W + (k + q) * FO + c0);
            #pragma unroll
            for (int r = 0; r < R; r++) {
                const float4 xv = *(const float4*)(Xs + (r0 + r) * xstride + k);
                acc0[r] = fmaf(xv.x, w0[0], acc0[r]);
                acc0[r] = fmaf(xv.y, w0[1], acc0[r]);
                acc0[r] = fmaf(xv.z, w0[2], acc0[r]);
                acc0[r] = fmaf(xv.w, w0[3], acc0[r]);
            }
        }
        #pragma unroll
        for (int r = 0; r < R; r++) {
            int n = r0 + r;
            if (FO >= 32 || lane < FO) Ys[n * FO + c0] = acc0[r] * invsh[n];
        }
    }
}

// ---------------- aggregation FO=32, direct write ----------------
__device__ __forceinline__ void agg32(
    const float* __restrict__ Ys, float* __restrict__ Out,
    const ushort4* __restrict__ csr4, const unsigned short* __restrict__ offsh,
    const float* __restrict__ invsh, const unsigned char* __restrict__ padsh,
    const float* __restrict__ bias, int warp, int lane)
{
    const float b0 = __ldg(bias + lane);
    for (int n = warp; n < NPG; n += NW) {
        int q0 = offsh[n] >> 2, q1 = offsh[n + 1] >> 2;
        float a0 = 0.f;
        for (int q = q0; q < q1; q++) {
            ushort4 ix = csr4[q];
            a0 += Ys[ix.x * 32 + lane];
            a0 += Ys[ix.y * 32 + lane];
            a0 += Ys[ix.z * 32 + lane];
            a0 += Ys[ix.w * 32 + lane];
        }
        float corr = 1.f - (float)padsh[n];
        a0 = fmaf(corr, Ys[n * 32 + lane], a0);
        Out[n * 32 + lane] = fmaxf(a0 * invsh[n] + b0, 0.f);
    }
}

// ---------------- resize-tap projection ----------------
template<int FO>
__device__ __forceinline__ void taps(const float* __restrict__ Hs, int stride,
                                     float* __restrict__ uout, int tid)
{
    for (int t = tid; t < 10 * FO; t += NT) {
        int p = t / FO, d = t % FO;
        float c = (p + 0.5f) * 51.2f - 0.5f;
        int i0 = (int)floorf(c);
        float w = c - (float)i0;
        uout[p * 64 + d] = Hs[i0 * stride + d] * (1.f - w) + Hs[(i0 + 1) * stride + d] * w;
    }
}

// ---------------- fused per-(graph,side) kernel + inline head on 2nd arrival ----------------
__global__ void __launch_bounds__(NT, 1)
k_fused(const float* __restrict__ x0, const float* __restrict__ x1,
        const float* __restrict__ W0, const float* __restrict__ b0,
        const float* __restrict__ W1, const float* __restrict__ b1,
        const float* __restrict__ W2, const float* __restrict__ b2,
        const int* __restrict__ ei, const int* __restrict__ ej,
        const float* __restrict__ cw0, const float* __restrict__ cb0,
        const float* __restrict__ cw1, const float* __restrict__ cb1,
        const float* __restrict__ cw2, const float* __restrict__ cb2,
        const float* __restrict__ mw0, const float* __restrict__ mb0,
        const float* __restrict__ mw1, const float* __restrict__ mb1,
        const float* __restrict__ mw2, const float* __restrict__ mb2,
        const float* __restrict__ mw3, const float* __restrict__ mb3,
        const float* __restrict__ mw4, const float* __restrict__ mb4,
        const float* __restrict__ sw,  const float* __restrict__ sb,
        float* __restrict__ out)
{
    extern __shared__ char smraw[];
    float*          xbuf  = (float*)(smraw + OFF_XBUF);
    float*          ybuf  = (float*)(smraw + OFF_YBUF);
    unsigned short* csr   = (unsigned short*)(smraw + OFF_CSR);
    const ushort4*  csr4  = (const ushort4*)csr;
    unsigned short* offsh = (unsigned short*)(smraw + OFF_OFFS);
    float*          invsh = (float*)(smraw + OFF_INV);
    unsigned char*  padsh = (unsigned char*)(smraw + OFF_PAD);
    int*            cnt   = (int*)(smraw + OFF_SCR);   // [512]
    int*            cur   = cnt + 512;                 // [512]
    int*            wtot  = cnt + 1024;                // [16]
    __shared__ int  lastflag;

    const int side = blockIdx.y, g = blockIdx.x;
    const int tid = threadIdx.x, warp = tid >> 5, lane = tid & 31;
    const int* E    = side ? ej : ei;
    const int* esrc = E + g * EPG;
    const int* edst = E + NEDGE + g * EPG;
    const float* Xg = (side ? x1 : x0) + (size_t)g * NPG * 64;

    // ---- phase A: preload X into xbuf (overlaps edge LDG latency) + cache edges + count ----
    unsigned short* srcc = (unsigned short*)ybuf;   // [8192]
    unsigned short* dstc = srcc + EPG;              // [8192]
    {
        const float4* src = (const float4*)Xg;
        float4* dst = (float4*)xbuf;
        for (int i = tid; i < 8192; i += NT) dst[i] = src[i];
    }
    if (tid < 512) cnt[tid] = 0;
    __syncthreads();
    for (int e = tid; e < EPG; e += NT) {
        int sv = esrc[e] & (NPG - 1), dv = edst[e] & (NPG - 1);
        srcc[e] = (unsigned short)sv;
        dstc[e] = (unsigned short)dv;
        atomicAdd(&cnt[dv], 1);
    }
    __syncthreads();

    // ---- scan of padded degrees ----
    int deg = 0, pc = 0, s_incl = 0, off = 0;
    if (tid < 512) {
        deg = cnt[tid];
        pc  = (deg + 3) & ~3;
        s_incl = pc;
        #pragma unroll
        for (int d = 1; d < 32; d <<= 1) {
            int v = __shfl_up_sync(0xffffffffu, s_incl, d);
            if (lane >= d) s_incl += v;
        }
        if (lane == 31) wtot[warp] = s_incl;
    }
    __syncthreads();
    if (tid < 16) {
        int t = wtot[tid];
        #pragma unroll
        for (int d = 1; d < 16; d <<= 1) {
            int v = __shfl_up_sync(0x0000ffffu, t, d);
            if (tid >= d) t += v;
        }
        wtot[tid] = t;
    }
    __syncthreads();
    if (tid < 512) {
        int base = warp ? wtot[warp - 1] : 0;
        off = base + s_incl - pc;
        offsh[tid] = (unsigned short)off;
        if (tid == 511) offsh[512] = (unsigned short)(off + pc);
        invsh[tid] = rsqrtf((float)deg + 1.0f);
        padsh[tid] = (unsigned char)(pc - deg);
        cur[tid] = off;
    }
    __syncthreads();

    // ---- fill pass: SMEM only, full block ----
    for (int e = tid; e < EPG; e += NT) {
        int dv = dstc[e];
        int p = atomicAdd(&cur[dv], 1);
        csr[p] = srcc[e];
    }
    if (tid < 512)
        for (int t = deg; t < pc; t++) csr[off + t] = (unsigned short)tid;
    __syncthreads();

    // ---- layer 0 XW: in-place in xbuf, all 32 warps ----
    xw0_pair_inplace(xbuf, W0, invsh, warp, lane);
    __syncthreads();

    // ---- agg0: gather xbuf, stage in regs, write back ----
    {
        float h0[16], h1[16];
        const float bb0 = __ldg(b0 + lane);
        const float bb1 = __ldg(b0 + lane + 32);
        #pragma unroll
        for (int it = 0; it < 16; it++) {
            int n = warp + it * NW;
            int q0 = offsh[n] >> 2, q1 = offsh[n + 1] >> 2;
            float a0 = 0.f, a1 = 0.f;
            for (int q = q0; q < q1; q++) {
                ushort4 ix = csr4[q];
                a0 += xbuf[ix.x * 64 + lane];  a1 += xbuf[ix.x * 64 + lane + 32];
                a0 += xbuf[ix.y * 64 + lane];  a1 += xbuf[ix.y * 64 + lane + 32];
                a0 += xbuf[ix.z * 64 + lane];  a1 += xbuf[ix.z * 64 + lane + 32];
                a0 += xbuf[ix.w * 64 + lane];  a1 += xbuf[ix.w * 64 + lane + 32];
            }
            float corr = 1.f - (float)padsh[n];
            a0 = fmaf(corr, xbuf[n * 64 + lane], a0);
            a1 = fmaf(corr, xbuf[n * 64 + lane + 32], a1);
            float inv = invsh[n];
            h0[it] = fmaxf(a0 * inv + bb0, 0.f);
            h1[it] = fmaxf(a1 * inv + bb1, 0.f);
        }
        __syncthreads();
        #pragma unroll
        for (int it = 0; it < 16; it++) {
            int n = warp + it * NW;
            xbuf[n * 64 + lane] = h0[it];
            xbuf[n * 64 + lane + 32] = h1[it];
        }
        __syncthreads();
    }

    // ---- taps0 + XW1 ----
    taps<64>(xbuf, 64, &g_u[side][0][g * 640], tid);
    xw_stage<64, 32, 8>(xbuf, 64, ybuf, W1, invsh, warp, lane);
    __syncthreads();

    // ---- agg1: ybuf -> xbuf ----
    agg32(ybuf, xbuf, csr4, offsh, invsh, padsh, b1, warp, lane);
    __syncthreads();

    // ---- taps1 + XW2 ----
    taps<32>(xbuf, 32, &g_u[side][1][g * 640], tid);
    xw_stage<32, 16, 8>(xbuf, 32, ybuf, W2, invsh, warp, lane);
    __syncthreads();

    // ---- fused agg2 + taps2: only the 20 tap rows ----
    float* tmp = (float*)cnt;
    if (warp < 20) {
        int p = warp >> 1;
        float c = (p + 0.5f) * 51.2f - 0.5f;
        int i0 = (int)floorf(c);
        int r = i0 + (warp & 1);
        int c0 = lane & 15;
        int q0 = offsh[r] >> 2, q1 = offsh[r + 1] >> 2;
        float a = 0.f;
        for (int q = q0; q < q1; q++) {
            ushort4 ix = csr4[q];
            a += ybuf[ix.x * 16 + c0];
            a += ybuf[ix.y * 16 + c0];
            a += ybuf[ix.z * 16 + c0];
            a += ybuf[ix.w * 16 + c0];
        }
        a = fmaf(1.f - (float)padsh[r], ybuf[r * 16 + c0], a);
        tmp[warp * 16 + c0] = a * invsh[r] + __ldg(b2 + c0);
    }
    __syncthreads();
    if (tid < 160) {
        int p = tid >> 4, d = tid & 15;
        float c = (p + 0.5f) * 51.2f - 0.5f;
        int i0 = (int)floorf(c);
        float w = c - (float)i0;
        g_u[side][2][g * 640 + p * 64 + d] =
            tmp[(2 * p) * 16 + d] * (1.f - w) + tmp[(2 * p + 1) * 16 + d] * w;
    }

    // ================= arrival: second block per graph runs the head =================
    __syncthreads();
    if (tid == 0) {
        __threadfence();
        lastflag = (atomicAdd(&g_done[g], 1) == 1);
    }
    __syncthreads();
    if (!lastflag) return;

    // SMEM reuse (everything above is dead)
    float* uiH   = (float*)smraw;        // [3*640]
    float* ujH   = uiH + 1920;           // [3*640]
    float* simH  = ujH + 1920;           // [300]
    float* featH = simH + 300;           // [2400]
    float* redH  = featH + 2400;         // [32*32]
    float* cwH   = redH + 1024;          // [216]
    float* cbH   = cwH + 216;            // [24]

    for (int t = tid; t < 1920; t += NT) {
        int l = t / 640, r = t - l * 640;
        uiH[t] = __ldcg(&g_u[0][l][g * 640 + r]);
        ujH[t] = __ldcg(&g_u[1][l][g * 640 + r]);
    }
    if (tid < 72) {
        cwH[tid]       = __ldg(cw0 + tid);
        cwH[72 + tid]  = __ldg(cw1 + tid);
        cwH[144 + tid] = __ldg(cw2 + tid);
    }
    if (tid >= 96 && tid < 104) {
        int c = tid - 96;
        cbH[c]      = __ldg(cb0 + c);
        cbH[8 + c]  = __ldg(cb1 + c);
        cbH[16 + c] = __ldg(cb2 + c);
    }
    __syncthreads();

    // sims: 300 warp-tasks over 32 warps
    for (int ent = warp; ent < 300; ent += NW) {
        int l = ent / 100, e = ent - l * 100;
        int p = e / 10, q = e - p * 10;
        int fo = 64 >> l;
        float s = 0.f;
        for (int d = lane; d < fo; d += 32)
            s = fmaf(uiH[l * 640 + p * 64 + d], ujH[l * 640 + q * 64 + d], s);
        #pragma unroll
        for (int o = 16; o; o >>= 1) s += __shfl_xor_sync(0xffffffffu, s, o);
        if (lane == 0) simH[ent] = s;
    }
    __syncthreads();

    // conv3x3 + relu -> feat[2400]
    for (int t = tid; t < 2400; t += NT) {
        int l = t / 800, u = t - l * 800;
        int ch = u / 100, rc = u - ch * 100, r = rc / 10, c = rc - r * 10;
        float acc = cbH[l * 8 + ch];
        #pragma unroll
        for (int dr = 0; dr < 3; dr++)
            #pragma unroll
            for (int dc = 0; dc < 3; dc++) {
                int rr = r + dr - 1, cc = c + dc - 1;
                if (rr >= 0 && rr < 10 && cc >= 0 && cc < 10)
                    acc = fmaf(cwH[l * 72 + ch * 9 + dr * 3 + dc], simH[l * 100 + rr * 10 + cc], acc);
            }
        featH[t] = fmaxf(acc, 0.f);
    }
    __syncthreads();

    // MLP0: 2400 -> 32, 32-way split-K
    {
        float acc = 0.f;
        for (int k = warp; k < 2400; k += 32)
            acc = fmaf(featH[k], __ldg(mw0 + k * 32 + lane), acc);
        redH[warp * 32 + lane] = acc;
    }
    __syncthreads();

    if (warp == 0) {
        float s = __ldg(mb0 + lane);
        #pragma unroll
        for (int p = 0; p < 32; p++) s += redH[p * 32 + lane];
        float a0v = fmaxf(s, 0.f);

        float a1v = (lane < 16) ? __ldg(mb1 + lane) : 0.f;
        #pragma unroll
        for (int k = 0; k < 32; k++) {
            float v = __shfl_sync(0xffffffffu, a0v, k);
            if (lane < 16) a1v = fmaf(v, __ldg(mw1 + k * 16 + lane), a1v);
        }
        a1v = fmaxf(a1v, 0.f);

        float a2v = (lane < 8) ? __ldg(mb2 + lane) : 0.f;
        #pragma unroll
        for (int k = 0; k < 16; k++) {
            float v = __shfl_sync(0xffffffffu, a1v, k);
            if (lane < 8) a2v = fmaf(v, __ldg(mw2 + k * 8 + lane), a2v);
        }
        a2v = fmaxf(a2v, 0.f);

        float a3v = (lane < 4) ? __ldg(mb3 + lane) : 0.f;
        #pragma unroll
        for (int k = 0; k < 8; k++) {
            float v = __shfl_sync(0xffffffffu, a2v, k);
            if (lane < 4) a3v = fmaf(v, __ldg(mw3 + k * 4 + lane), a3v);
        }
        a3v = fmaxf(a3v, 0.f);

        float v0 = __shfl_sync(0xffffffffu, a3v, 0);
        float v1 = __shfl_sync(0xffffffffu, a3v, 1);
        float v2 = __shfl_sync(0xffffffffu, a3v, 2);
        float v3 = __shfl_sync(0xffffffffu, a3v, 3);
        if (lane == 0) {
            float s4 = __ldg(mb4);
            s4 = fmaf(v0, __ldg(mw4 + 0), s4);
            s4 = fmaf(v1, __ldg(mw4 + 1), s4);
            s4 = fmaf(v2, __ldg(mw4 + 2), s4);
            s4 = fmaf(v3, __ldg(mw4 + 3), s4);
            float f = fmaxf(s4, 0.f);
            float sc = f * __ldg(sw) + __ldg(sb);
            out[g] = 1.f / (1.f + expf(-sc));
            g_done[g] = 0;   // reset for next graph replay
        }
    }
}

// ---------------- launch ----------------
extern "C" void kernel_launch(void* const* d_in, const int* in_sizes, int n_in,
                              void* d_out, int out_size) {
    const float* x_i = (const float*)d_in[0];
    const float* x_j = (const float*)d_in[1];
    const float* gw0 = (const float*)d_in[2];  const float* gb0 = (const float*)d_in[3];
    const float* gw1 = (const float*)d_in[4];  const float* gb1 = (const float*)d_in[5];
    const float* gw2 = (const float*)d_in[6];  const float* gb2 = (const float*)d_in[7];
    const float* cw0 = (const float*)d_in[8];  const float* cb0 = (const float*)d_in[9];
    const float* cw1 = (const float*)d_in[10]; const float* cb1 = (const float*)d_in[11];
    const float* cw2 = (const float*)d_in[12]; const float* cb2 = (const float*)d_in[13];
    const float* mw0 = (const float*)d_in[14]; const float* mb0 = (const float*)d_in[15];
    const float* mw1 = (const float*)d_in[16]; const float* mb1 = (const float*)d_in[17];
    const float* mw2 = (const float*)d_in[18]; const float* mb2 = (const float*)d_in[19];
    const float* mw3 = (const float*)d_in[20]; const float* mb3 = (const float*)d_in[21];
    const float* mw4 = (const float*)d_in[22]; const float* mb4 = (const float*)d_in[23];
    const float* sw  = (const float*)d_in[24]; const float* sb  = (const float*)d_in[25];
    const int*   ei  = (const int*)d_in[26];
    const int*   ej  = (const int*)d_in[27];

    cudaFuncSetAttribute(k_fused, cudaFuncAttributeMaxDynamicSharedMemorySize, SMEM_BYTES);

    k_fused<<<dim3(BGRAPH, 2), NT, SMEM_BYTES>>>(
        x_i, x_j, gw0, gb0, gw1, gb1, gw2, gb2, ei, ej,
        cw0, cb0, cw1, cb1, cw2, cb2,
        mw0, mb0, mw1, mb1, mw2, mb2, mw3, mb3, mw4, mb4,
        sw, sb, (float*)d_out);
}